// round 1
// baseline (speedup 1.0000x reference)
#include <cuda_runtime.h>
#include <math.h>

#define B_    2
#define T_    2048
#define D_    1024
#define HV_   16
#define HK_   8
#define DK_   64
#define DV_   64
#define KDIM_ 512
#define VDIM_ 1024
#define CONVD 2048
#define EPS_  1e-6f
#define NTOK  (B_*T_)   // 4096

// ---------------- static scratch (no allocations allowed) ----------------
__device__ float g_mixed[NTOK*CONVD];   // post-GEMM qkv (pre-conv)
__device__ float g_z[NTOK*VDIM_];
__device__ float g_beta[NTOK*HV_];
__device__ float g_gg[NTOK*HV_];
__device__ float g_qn[NTOK*HK_*DK_];
__device__ float g_kn[NTOK*HK_*DK_];
__device__ float g_v[NTOK*VDIM_];
__device__ float g_o[NTOK*VDIM_];
__device__ float g_on[NTOK*VDIM_];

// ---------------- fp32 SGEMM: C[M,N] = A[M,K] @ B[K,N], all row-major ----
// 128x128 tile, BK=8, 256 threads, 8x8 per thread. M,N,K multiples of 128/8.
__global__ __launch_bounds__(256) void sgemm128(
    const float* __restrict__ A, const float* __restrict__ Bm,
    float* __restrict__ C, int M, int N, int K)
{
    __shared__ float As[8][132];   // padded: avoids STS bank conflicts
    __shared__ float Bs[8][128];

    int tid = threadIdx.x;
    int bx = blockIdx.x, by = blockIdx.y;

    int arow = tid >> 1;            // 0..127
    int acol = (tid & 1) << 2;      // 0 or 4
    int brow = tid >> 5;            // 0..7
    int bcol = (tid & 31) << 2;     // 0..124
    int tm   = (tid >> 4) << 3;     // row offset of this thread's 8x8
    int tn   = (tid & 15) << 3;     // col offset

    const float* Ap = A + (long)(by*128 + arow)*K + acol;
    const float* Bp = Bm + (long)brow*N + bx*128 + bcol;

    float acc[8][8];
    #pragma unroll
    for (int i = 0; i < 8; i++)
        #pragma unroll
        for (int j = 0; j < 8; j++) acc[i][j] = 0.f;

    for (int k0 = 0; k0 < K; k0 += 8) {
        float4 av = *(const float4*)(Ap + k0);
        float4 bv = *(const float4*)(Bp + (long)k0*N);
        As[acol+0][arow] = av.x;
        As[acol+1][arow] = av.y;
        As[acol+2][arow] = av.z;
        As[acol+3][arow] = av.w;
        *(float4*)&Bs[brow][bcol] = bv;
        __syncthreads();
        #pragma unroll
        for (int kk = 0; kk < 8; kk++) {
            float af[8], bf[8];
            *(float4*)&af[0] = *(const float4*)&As[kk][tm];
            *(float4*)&af[4] = *(const float4*)&As[kk][tm+4];
            *(float4*)&bf[0] = *(const float4*)&Bs[kk][tn];
            *(float4*)&bf[4] = *(const float4*)&Bs[kk][tn+4];
            #pragma unroll
            for (int i = 0; i < 8; i++)
                #pragma unroll
                for (int j = 0; j < 8; j++)
                    acc[i][j] = fmaf(af[i], bf[j], acc[i][j]);
        }
        __syncthreads();
    }
    #pragma unroll
    for (int i = 0; i < 8; i++) {
        long off = (long)(by*128 + tm + i)*N + bx*128 + tn;
        float4 r0 = make_float4(acc[i][0], acc[i][1], acc[i][2], acc[i][3]);
        float4 r1 = make_float4(acc[i][4], acc[i][5], acc[i][6], acc[i][7]);
        *(float4*)(C + off)     = r0;
        *(float4*)(C + off + 4) = r1;
    }
}

// -------- beta = sigmoid(h@W_b), g = -exp(A_log)*softplus(h@W_a + dt_bias) --
__global__ __launch_bounds__(256) void betag_kernel(
    const float* __restrict__ hid, const float* __restrict__ Wb,
    const float* __restrict__ Wa, const float* __restrict__ dtb,
    const float* __restrict__ Alog)
{
    int row = blockIdx.x;       // 0..4095
    int tid = threadIdx.x;
    __shared__ float sh[D_];
    __shared__ float red[256];

    *(float4*)&sh[tid*4] = *(const float4*)(hid + (long)row*D_ + tid*4);
    __syncthreads();

    int c  = tid & 31;          // 0..31 : 0..15 -> beta, 16..31 -> g
    int sg = tid >> 5;          // 0..7
    const float* W = (c < 16) ? Wb : Wa;
    int cc = c & 15;
    int k0 = sg * 128;
    float acc = 0.f;
    #pragma unroll 8
    for (int k = 0; k < 128; k++)
        acc = fmaf(sh[k0 + k], W[(k0 + k)*HV_ + cc], acc);
    red[tid] = acc;
    __syncthreads();
    if (tid < 32) {
        float s = 0.f;
        #pragma unroll
        for (int si = 0; si < 8; si++) s += red[si*32 + c];
        if (c < 16) {
            g_beta[(long)row*HV_ + cc] = 1.f / (1.f + expf(-s));
        } else {
            float x  = s + dtb[cc];
            float sp = (x > 20.f) ? x : log1pf(expf(x));
            g_gg[(long)row*HV_ + cc] = -expf(Alog[cc]) * sp;
        }
    }
}

// -------- causal conv(KS=4) + SiLU + split q/k/v + l2norm q,k ------------
__global__ __launch_bounds__(256) void conv_kernel(
    const float* __restrict__ convw)
{
    int t = blockIdx.x, b = blockIdx.y;
    int tid = threadIdx.x;
    long row = (long)(b*T_ + t);
    __shared__ float sy[CONVD];

    #pragma unroll
    for (int j = 0; j < 8; j++) {
        int c = tid + j*256;
        float4 w = *(const float4*)(convw + c*4);
        float acc = g_mixed[row*CONVD + c] * w.w;
        if (t >= 1) acc = fmaf(g_mixed[(row-1)*CONVD + c], w.z, acc);
        if (t >= 2) acc = fmaf(g_mixed[(row-2)*CONVD + c], w.y, acc);
        if (t >= 3) acc = fmaf(g_mixed[(row-3)*CONVD + c], w.x, acc);
        sy[c] = acc / (1.f + expf(-acc));   // SiLU
    }
    __syncthreads();

    int wrp = tid >> 5, lane = tid & 31;
    // q head wrp : channels [wrp*64, wrp*64+64)
    {
        float y0 = sy[wrp*64 + lane], y1 = sy[wrp*64 + 32 + lane];
        float ss = y0*y0 + y1*y1;
        #pragma unroll
        for (int off = 16; off; off >>= 1) ss += __shfl_xor_sync(0xffffffffu, ss, off);
        float rs = rsqrtf(ss + EPS_) * 0.125f;   // * DK^-0.5
        g_qn[(row*HK_ + wrp)*64 + lane]      = y0 * rs;
        g_qn[(row*HK_ + wrp)*64 + 32 + lane] = y1 * rs;
    }
    // k head wrp : channels [512 + wrp*64, ...)
    {
        float y0 = sy[KDIM_ + wrp*64 + lane], y1 = sy[KDIM_ + wrp*64 + 32 + lane];
        float ss = y0*y0 + y1*y1;
        #pragma unroll
        for (int off = 16; off; off >>= 1) ss += __shfl_xor_sync(0xffffffffu, ss, off);
        float rs = rsqrtf(ss + EPS_);
        g_kn[(row*HK_ + wrp)*64 + lane]      = y0 * rs;
        g_kn[(row*HK_ + wrp)*64 + 32 + lane] = y1 * rs;
    }
    // v : channels [1024, 2048)
    #pragma unroll
    for (int j = 0; j < 4; j++) {
        int c = tid + j*256;
        g_v[row*VDIM_ + c] = sy[1024 + c];
    }
}

// -------- gated delta-rule recurrence, state split: 2 blocks per (b,h) ---
__global__ __launch_bounds__(256) void recurrence_kernel()
{
    int blk  = blockIdx.x;       // 0..63
    int bh   = blk >> 1;         // 0..31
    int half = blk & 1;          // state column half
    int b  = bh >> 4;
    int h  = bh & 15;
    int kh = h >> 1;             // GQA: repeat(.,2) -> h//2
    int tid = threadIdx.x;
    int colIdx = tid & 31;       // local column (0..31)
    int col  = colIdx + half*32; // global DV column
    int rseg = tid >> 5;         // row segment 0..7 (8 rows each)

    __shared__ float sq[2][64], sk[2][64], sv[2][32];
    __shared__ float sg[2], sb[2];
    __shared__ float red[256], red2[256];

    float S[8];
    #pragma unroll
    for (int i = 0; i < 8; i++) S[i] = 0.f;

    // preload t=0
    {
        long base = (long)(b*T_);
        if (tid < 64)       sq[0][tid]     = g_qn[(base*HK_ + kh)*64 + tid];
        else if (tid < 128) sk[0][tid-64]  = g_kn[(base*HK_ + kh)*64 + (tid-64)];
        else if (tid < 160) sv[0][tid-128] = g_v[(base*HV_ + h)*64 + half*32 + (tid-128)];
        else if (tid == 160) sg[0] = g_gg[base*HV_ + h];
        else if (tid == 161) sb[0] = g_beta[base*HV_ + h];
    }
    __syncthreads();

    int p = 0;
    for (int t = 0; t < T_; t++) {
        // prefetch t+1 into registers (hide global latency behind compute)
        float pre = 0.f;
        if (t + 1 < T_) {
            long base = (long)(b*T_ + t + 1);
            if (tid < 64)       pre = g_qn[(base*HK_ + kh)*64 + tid];
            else if (tid < 128) pre = g_kn[(base*HK_ + kh)*64 + (tid-64)];
            else if (tid < 160) pre = g_v[(base*HV_ + h)*64 + half*32 + (tid-128)];
            else if (tid == 160) pre = g_gg[base*HV_ + h];
            else if (tid == 161) pre = g_beta[base*HV_ + h];
        }
        float eg = expf(sg[p]);
        float bt = sb[p];
        float vv = sv[p][colIdx];

        // pass 1: decay + partial kv = k . S_col
        float kvp = 0.f;
        #pragma unroll
        for (int i = 0; i < 8; i++) {
            int r = rseg*8 + i;
            S[i] *= eg;
            kvp = fmaf(sk[p][r], S[i], kvp);
        }
        red[tid] = kvp;
        __syncthreads();
        float kv = 0.f;
        #pragma unroll
        for (int si = 0; si < 8; si++) kv += red[si*32 + colIdx];
        float delta = (vv - kv) * bt;

        // pass 2: rank-1 update + partial o = q . S_col
        float op = 0.f;
        #pragma unroll
        for (int i = 0; i < 8; i++) {
            int r = rseg*8 + i;
            S[i] = fmaf(sk[p][r], delta, S[i]);
            op = fmaf(sq[p][r], S[i], op);
        }
        red2[tid] = op;

        // stage prefetched t+1 into the other shared buffer
        int q = p ^ 1;
        if (t + 1 < T_) {
            if (tid < 64)       sq[q][tid]     = pre;
            else if (tid < 128) sk[q][tid-64]  = pre;
            else if (tid < 160) sv[q][tid-128] = pre;
            else if (tid == 160) sg[q] = pre;
            else if (tid == 161) sb[q] = pre;
        }
        __syncthreads();

        if (rseg == 0) {
            float ov = 0.f;
            #pragma unroll
            for (int si = 0; si < 8; si++) ov += red2[si*32 + colIdx];
            g_o[(((long)(b*T_ + t))*HV_ + h)*64 + col] = ov;
        }
        p = q;
    }
}

// -------- gated RMSNorm: rmsnorm(o)*norm_w*silu(z) ------------------------
__global__ __launch_bounds__(256) void gnorm_kernel(const float* __restrict__ nw)
{
    int t = blockIdx.x, b = blockIdx.y;
    long row = (long)(b*T_ + t);
    int wrp = threadIdx.x >> 5, lane = threadIdx.x & 31;
    #pragma unroll
    for (int hh = wrp; hh < HV_; hh += 8) {
        float o0 = g_o[(row*HV_ + hh)*64 + lane];
        float o1 = g_o[(row*HV_ + hh)*64 + 32 + lane];
        float ss = o0*o0 + o1*o1;
        #pragma unroll
        for (int off = 16; off; off >>= 1) ss += __shfl_xor_sync(0xffffffffu, ss, off);
        float rs = rsqrtf(ss * (1.f/64.f) + EPS_);
        float z0 = g_z[row*VDIM_ + hh*64 + lane];
        float z1 = g_z[row*VDIM_ + hh*64 + 32 + lane];
        g_on[row*VDIM_ + hh*64 + lane]      = o0 * rs * nw[lane]    * (z0 / (1.f + expf(-z0)));
        g_on[row*VDIM_ + hh*64 + 32 + lane] = o1 * rs * nw[lane+32] * (z1 / (1.f + expf(-z1)));
    }
}

// --------------------------------------------------------------------------
extern "C" void kernel_launch(void* const* d_in, const int* in_sizes, int n_in,
                              void* d_out, int out_size)
{
    (void)in_sizes; (void)n_in; (void)out_size;
    const float* hid   = (const float*)d_in[0];
    const float* Wqkv  = (const float*)d_in[1];
    const float* Wz    = (const float*)d_in[2];
    const float* Wb    = (const float*)d_in[3];
    const float* Wa    = (const float*)d_in[4];
    const float* dtb   = (const float*)d_in[5];
    const float* Alog  = (const float*)d_in[6];
    const float* convw = (const float*)d_in[7];
    const float* nw    = (const float*)d_in[8];
    const float* Wout  = (const float*)d_in[9];
    float* out = (float*)d_out;

    float *mixed, *z, *onrm;
    cudaGetSymbolAddress((void**)&mixed, g_mixed);
    cudaGetSymbolAddress((void**)&z,     g_z);
    cudaGetSymbolAddress((void**)&onrm,  g_on);

    // 1) mixed_qkv = hidden @ W_qkv   [4096,1024]x[1024,2048]
    sgemm128<<<dim3(CONVD/128, NTOK/128), 256>>>(hid, Wqkv, mixed, NTOK, CONVD, D_);
    // 2) z = hidden @ W_z             [4096,1024]x[1024,1024]
    sgemm128<<<dim3(VDIM_/128, NTOK/128), 256>>>(hid, Wz, z, NTOK, VDIM_, D_);
    // 3) beta / g
    betag_kernel<<<NTOK, 256>>>(hid, Wb, Wa, dtb, Alog);
    // 4) conv + silu + split + l2norm
    conv_kernel<<<dim3(T_, B_), 256>>>(convw);
    // 5) gated delta-rule recurrence
    recurrence_kernel<<<64, 256>>>();
    // 6) gated RMSNorm * silu(z)
    gnorm_kernel<<<dim3(T_, B_), 256>>>(nw);
    // 7) out = o_norm @ W_out
    sgemm128<<<dim3(D_/128, NTOK/128), 256>>>(onrm, Wout, out, NTOK, D_, VDIM_);
}

// round 3
// speedup vs baseline: 1.1327x; 1.1327x over previous
#include <cuda_runtime.h>
#include <cuda_bf16.h>
#include <math.h>
#include <stdint.h>

#define B_    2
#define T_    2048
#define D_    1024
#define HV_   16
#define HK_   8
#define KDIM_ 512
#define VDIM_ 1024
#define CONVD 2048
#define EPS_  1e-6f
#define NTOK  (B_*T_)   // 4096

// ======================= PTX helpers ======================================
__device__ __forceinline__ uint32_t smem_to_u32(const void* p) {
    uint32_t a;
    asm("{ .reg .u64 t; cvta.to.shared.u64 t, %1; cvt.u32.u64 %0, t; }" : "=r"(a) : "l"(p));
    return a;
}
__device__ __forceinline__ void ldsm_x4(uint32_t* r, uint32_t addr) {
    asm volatile("ldmatrix.sync.aligned.m8n8.x4.shared.b16 {%0,%1,%2,%3}, [%4];"
        : "=r"(r[0]), "=r"(r[1]), "=r"(r[2]), "=r"(r[3]) : "r"(addr));
}
__device__ __forceinline__ void mma16816(float* c, const uint32_t* a, const uint32_t* b) {
    asm volatile("mma.sync.aligned.m16n8k16.row.col.f32.bf16.bf16.f32 "
        "{%0,%1,%2,%3}, {%4,%5,%6,%7}, {%8,%9}, {%0,%1,%2,%3};"
        : "+f"(c[0]), "+f"(c[1]), "+f"(c[2]), "+f"(c[3])
        : "r"(a[0]), "r"(a[1]), "r"(a[2]), "r"(a[3]), "r"(b[0]), "r"(b[1]));
}
#define CP16(sm, gp) asm volatile("cp.async.cg.shared.global [%0], [%1], 16;" :: "r"(sm), "l"(gp))
#define CP_COMMIT()  asm volatile("cp.async.commit_group;" ::: "memory")
#define CP_WAIT1()   asm volatile("cp.async.wait_group 1;" ::: "memory")
#define CP_WAIT0()   asm volatile("cp.async.wait_group 0;" ::: "memory")

// byte offset of (row, kc) 16B-unit in a [128 x 32bf16] tile, xor-swizzled
__device__ __forceinline__ uint32_t tunit(int row, int kc) {
    return (uint32_t)((row*4 + (kc ^ ((row >> 1) & 3))) * 16);
}

// ======================= static scratch ===================================
__device__ float g_mixed[NTOK*CONVD];
__device__ float g_z[NTOK*VDIM_];
__device__ float g_beta[NTOK*HV_];
__device__ float g_gg[NTOK*HV_];
__device__ float g_qn[NTOK*HK_*64];
__device__ float g_kn[NTOK*HK_*64];
__device__ float g_v[NTOK*VDIM_];
__device__ float g_o[NTOK*VDIM_];
__device__ __nv_bfloat16 g_hid_h[NTOK*D_],  g_hid_l[NTOK*D_];
__device__ __nv_bfloat16 g_wq_h[CONVD*D_],  g_wq_l[CONVD*D_];     // [N,K]
__device__ __nv_bfloat16 g_wz_h[VDIM_*D_],  g_wz_l[VDIM_*D_];
__device__ __nv_bfloat16 g_wo_h[D_*VDIM_],  g_wo_l[D_*VDIM_];
__device__ __nv_bfloat16 g_on_h[NTOK*VDIM_], g_on_l[NTOK*VDIM_];

// ======================= fp32 -> bf16 hi/lo ===============================
__global__ __launch_bounds__(256) void cvt_hilo(const float* __restrict__ src,
        __nv_bfloat16* __restrict__ hi, __nv_bfloat16* __restrict__ lo, int n4)
{
    int i = blockIdx.x*256 + threadIdx.x;
    if (i >= n4) return;
    float4 x = ((const float4*)src)[i];
    __nv_bfloat16 h0 = __float2bfloat16(x.x), h1 = __float2bfloat16(x.y);
    __nv_bfloat16 h2 = __float2bfloat16(x.z), h3 = __float2bfloat16(x.w);
    __nv_bfloat162 hh0 = {h0,h1}, hh1 = {h2,h3};
    __nv_bfloat162 ll0 = {__float2bfloat16(x.x - __bfloat162float(h0)),
                          __float2bfloat16(x.y - __bfloat162float(h1))};
    __nv_bfloat162 ll1 = {__float2bfloat16(x.z - __bfloat162float(h2)),
                          __float2bfloat16(x.w - __bfloat162float(h3))};
    ((__nv_bfloat162*)hi)[2*i]   = hh0; ((__nv_bfloat162*)hi)[2*i+1] = hh1;
    ((__nv_bfloat162*)lo)[2*i]   = ll0; ((__nv_bfloat162*)lo)[2*i+1] = ll1;
}

// ============ transpose + convert: W[K,N] fp32 -> Wt[N,K] bf16 hi/lo ======
__global__ __launch_bounds__(256) void tconv_hilo(const float* __restrict__ W,
        __nv_bfloat16* __restrict__ thi, __nv_bfloat16* __restrict__ tlo, int K, int N)
{
    __shared__ float tile[32][33];
    int n0 = blockIdx.x*32, k0 = blockIdx.y*32;
    int tx = threadIdx.x, ty = threadIdx.y;   // 32 x 8
    #pragma unroll
    for (int j = 0; j < 32; j += 8)
        tile[ty+j][tx] = W[(long)(k0+ty+j)*N + n0 + tx];
    __syncthreads();
    #pragma unroll
    for (int j = 0; j < 32; j += 8) {
        float x = tile[tx][ty+j];
        __nv_bfloat16 h = __float2bfloat16(x);
        long o = (long)(n0+ty+j)*K + k0 + tx;
        thi[o] = h;
        tlo[o] = __float2bfloat16(x - __bfloat162float(h));
    }
}

// =============== bf16 hi/lo (3-MMA) tensor-core GEMM ======================
// C[M,N] = A[M,K] @ W[K,N]; A hi/lo [M,K] row-major, W hi/lo [N,K] row-major.
// 128x128x32 tiles, 256 thr, cp.async double-buffer, mma.m16n8k16.
#define STAGE_B 32768   // Ah 8K | Al 8K | Bh 8K | Bl 8K
__global__ __launch_bounds__(256) void gemm_mma(
    const __nv_bfloat16* __restrict__ Ah, const __nv_bfloat16* __restrict__ Al,
    const __nv_bfloat16* __restrict__ Bh, const __nv_bfloat16* __restrict__ Bl,
    float* __restrict__ C, int M, int N, int K)
{
    extern __shared__ __align__(128) char smem[];
    uint32_t sb = smem_to_u32(smem);
    int tid = threadIdx.x, lane = tid & 31, wid = tid >> 5;
    int wm = wid & 3, wn = wid >> 2;        // 4 x 2 warp grid
    int bx = blockIdx.x, by = blockIdx.y;
    const int NC = K >> 5;

    float acc[2][8][4];
    #pragma unroll
    for (int i = 0; i < 2; i++)
        #pragma unroll
        for (int j = 0; j < 8; j++)
            #pragma unroll
            for (int q = 0; q < 4; q++) acc[i][j][q] = 0.f;

    // cp.async loader: 512 16B-units per tile, 2 per thread per tile
    int ur[2], uk[2];
    ur[0] = tid >> 2;         uk[0] = tid & 3;
    ur[1] = (tid + 256) >> 2; uk[1] = tid & 3;

    #define LOAD_CHUNK(ic, s) do { \
        long kof = (long)(ic) * 32; \
        uint32_t st = sb + (s)*STAGE_B; \
        _Pragma("unroll") \
        for (int uu = 0; uu < 2; uu++) { \
            int row = ur[uu], kc = uk[uu]; \
            uint32_t d = st + tunit(row, kc); \
            long ao = (long)(by*128 + row)*K + kof + kc*8; \
            long bo = (long)(bx*128 + row)*K + kof + kc*8; \
            CP16(d,         Ah + ao); \
            CP16(d + 8192,  Al + ao); \
            CP16(d + 16384, Bh + bo); \
            CP16(d + 24576, Bl + bo); \
        } \
        CP_COMMIT(); \
    } while (0)

    LOAD_CHUNK(0, 0);

    int lr = lane & 15, lk = lane >> 4;
    for (int ic = 0; ic < NC; ic++) {
        int s = ic & 1;
        if (ic + 1 < NC) { LOAD_CHUNK(ic + 1, s ^ 1); CP_WAIT1(); }
        else             { CP_WAIT0(); }
        __syncthreads();

        uint32_t pAh = sb + s*STAGE_B, pAl = pAh + 8192;
        uint32_t pBh = pAh + 16384,    pBl = pAh + 24576;
        #pragma unroll
        for (int ks = 0; ks < 2; ks++) {
            uint32_t ah[2][4], al[2][4], bh[8][2], bl[8][2];
            #pragma unroll
            for (int mt = 0; mt < 2; mt++) {
                uint32_t off = tunit(wm*32 + mt*16 + lr, ks*2 + lk);
                ldsm_x4(ah[mt], pAh + off);
                ldsm_x4(al[mt], pAl + off);
            }
            #pragma unroll
            for (int bp = 0; bp < 4; bp++) {
                uint32_t off = tunit(wn*64 + bp*16 + lr, ks*2 + lk);
                uint32_t t[4];
                ldsm_x4(t, pBh + off);
                bh[bp*2][0]=t[0]; bh[bp*2][1]=t[2]; bh[bp*2+1][0]=t[1]; bh[bp*2+1][1]=t[3];
                ldsm_x4(t, pBl + off);
                bl[bp*2][0]=t[0]; bl[bp*2][1]=t[2]; bl[bp*2+1][0]=t[1]; bl[bp*2+1][1]=t[3];
            }
            #pragma unroll
            for (int mt = 0; mt < 2; mt++)
                #pragma unroll
                for (int nt = 0; nt < 8; nt++) {
                    mma16816(acc[mt][nt], ah[mt], bh[nt]);
                    mma16816(acc[mt][nt], ah[mt], bl[nt]);
                    mma16816(acc[mt][nt], al[mt], bh[nt]);
                }
        }
        __syncthreads();
    }

    // epilogue: fp32 accumulators -> C
    #pragma unroll
    for (int mt = 0; mt < 2; mt++)
        #pragma unroll
        for (int nt = 0; nt < 8; nt++) {
            long r = by*128 + wm*32 + mt*16 + (lane >> 2);
            long c = bx*128 + wn*64 + nt*8 + (lane & 3)*2;
            *(float2*)&C[r*N + c]       = make_float2(acc[mt][nt][0], acc[mt][nt][1]);
            *(float2*)&C[(r+8)*N + c]   = make_float2(acc[mt][nt][2], acc[mt][nt][3]);
        }
}

// ======================= beta / g projections =============================
__global__ __launch_bounds__(256) void betag_kernel(
    const float* __restrict__ hid, const float* __restrict__ Wb,
    const float* __restrict__ Wa, const float* __restrict__ dtb,
    const float* __restrict__ Alog)
{
    int row = blockIdx.x;
    int tid = threadIdx.x;
    __shared__ float sh[D_];
    __shared__ float red[256];
    *(float4*)&sh[tid*4] = *(const float4*)(hid + (long)row*D_ + tid*4);
    __syncthreads();
    int c  = tid & 31, sg = tid >> 5;
    const float* W = (c < 16) ? Wb : Wa;
    int cc = c & 15, k0 = sg * 128;
    float acc = 0.f;
    #pragma unroll 8
    for (int k = 0; k < 128; k++)
        acc = fmaf(sh[k0 + k], W[(k0 + k)*HV_ + cc], acc);
    red[tid] = acc;
    __syncthreads();
    if (tid < 32) {
        float s = 0.f;
        #pragma unroll
        for (int si = 0; si < 8; si++) s += red[si*32 + c];
        if (c < 16) g_beta[(long)row*HV_ + cc] = 1.f / (1.f + expf(-s));
        else {
            float x  = s + dtb[cc];
            float sp = (x > 20.f) ? x : log1pf(expf(x));
            g_gg[(long)row*HV_ + cc] = -expf(Alog[cc]) * sp;
        }
    }
}

// ============== causal conv + SiLU + split + l2norm =======================
__global__ __launch_bounds__(256) void conv_kernel(const float* __restrict__ convw)
{
    int t = blockIdx.x, b = blockIdx.y;
    int tid = threadIdx.x;
    long row = (long)(b*T_ + t);
    __shared__ float sy[CONVD];
    #pragma unroll
    for (int j = 0; j < 8; j++) {
        int c = tid + j*256;
        float4 w = *(const float4*)(convw + c*4);
        float acc = g_mixed[row*CONVD + c] * w.w;
        if (t >= 1) acc = fmaf(g_mixed[(row-1)*CONVD + c], w.z, acc);
        if (t >= 2) acc = fmaf(g_mixed[(row-2)*CONVD + c], w.y, acc);
        if (t >= 3) acc = fmaf(g_mixed[(row-3)*CONVD + c], w.x, acc);
        sy[c] = acc / (1.f + expf(-acc));
    }
    __syncthreads();
    int wrp = tid >> 5, lane = tid & 31;
    {
        float y0 = sy[wrp*64 + lane], y1 = sy[wrp*64 + 32 + lane];
        float ss = y0*y0 + y1*y1;
        #pragma unroll
        for (int off = 16; off; off >>= 1) ss += __shfl_xor_sync(0xffffffffu, ss, off);
        float rs = rsqrtf(ss + EPS_) * 0.125f;
        g_qn[(row*HK_ + wrp)*64 + lane]      = y0 * rs;
        g_qn[(row*HK_ + wrp)*64 + 32 + lane] = y1 * rs;
    }
    {
        float y0 = sy[KDIM_ + wrp*64 + lane], y1 = sy[KDIM_ + wrp*64 + 32 + lane];
        float ss = y0*y0 + y1*y1;
        #pragma unroll
        for (int off = 16; off; off >>= 1) ss += __shfl_xor_sync(0xffffffffu, ss, off);
        float rs = rsqrtf(ss + EPS_);
        g_kn[(row*HK_ + wrp)*64 + lane]      = y0 * rs;
        g_kn[(row*HK_ + wrp)*64 + 32 + lane] = y1 * rs;
    }
    #pragma unroll
    for (int j = 0; j < 4; j++) {
        int c = tid + j*256;
        g_v[row*VDIM_ + c] = sy[1024 + c];
    }
}

// ======= gated delta recurrence: lazy update, 1 barrier/step ==============
__global__ __launch_bounds__(128) void recurrence_kernel()
{
    int blk = blockIdx.x;
    int bh = blk >> 2, qd = blk & 3;
    int b = bh >> 4, h = bh & 15, kh = h >> 1;
    int tid = threadIdx.x;
    int colIdx = tid >> 3;
    int rseg = tid & 7;
    int col = qd*16 + colIdx;

    __shared__ float sq[2][64], sk[2][64], sv[2][16], sgb[2][2];
    __shared__ float rkv[2][128], ro[2][128], rqk[2][8];

    float S[8], kr[8];
    float dprev = 0.f;
    #pragma unroll
    for (int i = 0; i < 8; i++) { S[i] = 0.f; kr[i] = 0.f; }

    {
        long base = (long)(b*T_);
        if (tid < 32)      { float2 v = *(const float2*)(g_qn + (base*HK_+kh)*64 + 2*tid);      sq[0][2*tid]=v.x; sq[0][2*tid+1]=v.y; }
        else if (tid < 64) { int l=tid-32; float2 v = *(const float2*)(g_kn + (base*HK_+kh)*64 + 2*l); sk[0][2*l]=v.x; sk[0][2*l+1]=v.y; }
        else if (tid < 72) { int l=tid-64; float2 v = *(const float2*)(g_v + (base*HV_+h)*64 + qd*16 + 2*l); sv[0][2*l]=v.x; sv[0][2*l+1]=v.y; }
        else if (tid == 72) sgb[0][0] = g_gg[base*HV_+h];
        else if (tid == 73) sgb[0][1] = g_beta[base*HV_+h];
    }
    __syncthreads();

    int p = 0;
    for (int t = 0; t < T_; t++) {
        int par = t & 1;
        float2 pre = make_float2(0.f, 0.f);
        if (t + 1 < T_) {
            long base = (long)(b*T_ + t + 1);
            if (tid < 32)      pre = *(const float2*)(g_qn + (base*HK_+kh)*64 + 2*tid);
            else if (tid < 64) pre = *(const float2*)(g_kn + (base*HK_+kh)*64 + 2*(tid-32));
            else if (tid < 72) pre = *(const float2*)(g_v + (base*HV_+h)*64 + qd*16 + 2*(tid-64));
            else if (tid == 72) pre.x = g_gg[base*HV_+h];
            else if (tid == 73) pre.x = g_beta[base*HV_+h];
        }
        float eg = expf(sgb[p][0]);
        float bt = sgb[p][1];
        float vv = sv[p][colIdx];
        float kvp = 0.f, op = 0.f, qkp = 0.f;
        #pragma unroll
        for (int i = 0; i < 8; i++) {
            int r = rseg*8 + i;
            float kn = sk[p][r], qn = sq[p][r];
            S[i] = fmaf(kr[i], dprev, S[i]) * eg;     // deferred update + decay
            kvp = fmaf(kn, S[i], kvp);
            op  = fmaf(qn, S[i], op);
            qkp = fmaf(qn, kn, qkp);
            kr[i] = kn;
        }
        rkv[par][tid] = kvp;
        ro[par][tid]  = op;
        if (colIdx == 0) rqk[par][rseg] = qkp;
        int np = p ^ 1;
        if (t + 1 < T_) {
            if (tid < 32)      { sq[np][2*tid]=pre.x; sq[np][2*tid+1]=pre.y; }
            else if (tid < 64) { int l=tid-32; sk[np][2*l]=pre.x; sk[np][2*l+1]=pre.y; }
            else if (tid < 72) { int l=tid-64; sv[np][2*l]=pre.x; sv[np][2*l+1]=pre.y; }
            else if (tid == 72) sgb[np][0] = pre.x;
            else if (tid == 73) sgb[np][1] = pre.x;
        }
        __syncthreads();
        float kv = 0.f, os = 0.f, qk = 0.f;
        #pragma unroll
        for (int s2 = 0; s2 < 8; s2++) {
            kv += rkv[par][colIdx*8 + s2];
            os += ro[par][colIdx*8 + s2];
            qk += rqk[par][s2];
        }
        float delta = (vv - kv) * bt;
        dprev = delta;
        if (rseg == 0)
            g_o[(((long)(b*T_+t))*HV_ + h)*64 + col] = fmaf(qk, delta, os);
        p = np;
    }
}

// ========== gated RMSNorm * silu(z), emits bf16 hi/lo for GEMM3 ===========
__global__ __launch_bounds__(256) void gnorm_kernel(const float* __restrict__ nw)
{
    int t = blockIdx.x, b = blockIdx.y;
    long row = (long)(b*T_ + t);
    int wrp = threadIdx.x >> 5, lane = threadIdx.x & 31;
    #pragma unroll
    for (int hh = wrp; hh < HV_; hh += 8) {
        float o0 = g_o[(row*HV_ + hh)*64 + lane];
        float o1 = g_o[(row*HV_ + hh)*64 + 32 + lane];
        float ss = o0*o0 + o1*o1;
        #pragma unroll
        for (int off = 16; off; off >>= 1) ss += __shfl_xor_sync(0xffffffffu, ss, off);
        float rs = rsqrtf(ss * (1.f/64.f) + EPS_);
        float z0 = g_z[row*VDIM_ + hh*64 + lane];
        float z1 = g_z[row*VDIM_ + hh*64 + 32 + lane];
        float v0 = o0 * rs * nw[lane]      * (z0 / (1.f + expf(-z0)));
        float v1 = o1 * rs * nw[lane + 32] * (z1 / (1.f + expf(-z1)));
        long i0 = row*VDIM_ + hh*64 + lane;
        __nv_bfloat16 h0 = __float2bfloat16(v0);
        __nv_bfloat16 h1 = __float2bfloat16(v1);
        g_on_h[i0]      = h0;
        g_on_h[i0 + 32] = h1;
        g_on_l[i0]      = __float2bfloat16(v0 - __bfloat162float(h0));
        g_on_l[i0 + 32] = __float2bfloat16(v1 - __bfloat162float(h1));
    }
}

// ==========================================================================
extern "C" void kernel_launch(void* const* d_in, const int* in_sizes, int n_in,
                              void* d_out, int out_size)
{
    (void)in_sizes; (void)n_in; (void)out_size;
    const float* hid   = (const float*)d_in[0];
    const float* Wqkv  = (const float*)d_in[1];
    const float* Wz    = (const float*)d_in[2];
    const float* Wb    = (const float*)d_in[3];
    const float* Wa    = (const float*)d_in[4];
    const float* dtb   = (const float*)d_in[5];
    const float* Alog  = (const float*)d_in[6];
    const float* convw = (const float*)d_in[7];
    const float* nw    = (const float*)d_in[8];
    const float* Wout  = (const float*)d_in[9];
    float* out = (float*)d_out;

    float *mixed, *zz;
    __nv_bfloat16 *hh, *hl, *wqh, *wql, *wzh, *wzl, *woh, *wol, *onh, *onl;
    cudaGetSymbolAddress((void**)&mixed, g_mixed);
    cudaGetSymbolAddress((void**)&zz,  g_z);
    cudaGetSymbolAddress((void**)&hh,  g_hid_h);  cudaGetSymbolAddress((void**)&hl,  g_hid_l);
    cudaGetSymbolAddress((void**)&wqh, g_wq_h);   cudaGetSymbolAddress((void**)&wql, g_wq_l);
    cudaGetSymbolAddress((void**)&wzh, g_wz_h);   cudaGetSymbolAddress((void**)&wzl, g_wz_l);
    cudaGetSymbolAddress((void**)&woh, g_wo_h);   cudaGetSymbolAddress((void**)&wol, g_wo_l);
    cudaGetSymbolAddress((void**)&onh, g_on_h);   cudaGetSymbolAddress((void**)&onl, g_on_l);

    static int smem_set = 0;
    if (!smem_set) {
        cudaFuncSetAttribute(gemm_mma, cudaFuncAttributeMaxDynamicSharedMemorySize, 2*STAGE_B);
        smem_set = 1;
    }

    // conversions
    cvt_hilo<<<(NTOK*D_/4 + 255)/256, 256>>>(hid, hh, hl, NTOK*D_/4);
    tconv_hilo<<<dim3(CONVD/32, D_/32), dim3(32,8)>>>(Wqkv, wqh, wql, D_, CONVD);
    tconv_hilo<<<dim3(VDIM_/32, D_/32), dim3(32,8)>>>(Wz, wzh, wzl, D_, VDIM_);
    tconv_hilo<<<dim3(D_/32, VDIM_/32), dim3(32,8)>>>(Wout, woh, wol, VDIM_, D_);

    // GEMM1: mixed = hid @ Wqkv
    gemm_mma<<<dim3(CONVD/128, NTOK/128), 256, 2*STAGE_B>>>(hh, hl, wqh, wql, mixed, NTOK, CONVD, D_);
    // GEMM2: z = hid @ Wz
    gemm_mma<<<dim3(VDIM_/128, NTOK/128), 256, 2*STAGE_B>>>(hh, hl, wzh, wzl, zz, NTOK, VDIM_, D_);
    // beta / g
    betag_kernel<<<NTOK, 256>>>(hid, Wb, Wa, dtb, Alog);
    // conv + silu + split + l2norm
    conv_kernel<<<dim3(T_, B_), 256>>>(convw);
    // recurrence
    recurrence_kernel<<<128, 128>>>();
    // gated RMSNorm -> bf16 hi/lo
    gnorm_kernel<<<dim3(T_, B_), 256>>>(nw);
    // GEMM3: out = on @ Wout
    gemm_mma<<<dim3(D_/128, NTOK/128), 256, 2*STAGE_B>>>(onh, onl, woh, wol, out, NTOK, D_, VDIM_);
}

// round 4
// speedup vs baseline: 1.5899x; 1.4036x over previous
#include <cuda_runtime.h>
#include <cuda_bf16.h>
#include <math.h>
#include <stdint.h>

#define B_    2
#define T_    2048
#define D_    1024
#define HV_   16
#define HK_   8
#define KDIM_ 512
#define VDIM_ 1024
#define CONVD 2048
#define MIXW  3072          // fused GEMM width: [qkv 2048 | z 1024]
#define EPS_  1e-6f
#define NTOK  (B_*T_)       // 4096

// ======================= PTX helpers ======================================
__device__ __forceinline__ uint32_t smem_to_u32(const void* p) {
    uint32_t a;
    asm("{ .reg .u64 t; cvta.to.shared.u64 t, %1; cvt.u32.u64 %0, t; }" : "=r"(a) : "l"(p));
    return a;
}
__device__ __forceinline__ void ldsm_x4(uint32_t* r, uint32_t addr) {
    asm volatile("ldmatrix.sync.aligned.m8n8.x4.shared.b16 {%0,%1,%2,%3}, [%4];"
        : "=r"(r[0]), "=r"(r[1]), "=r"(r[2]), "=r"(r[3]) : "r"(addr));
}
__device__ __forceinline__ void mma16816(float* c, const uint32_t* a, const uint32_t* b) {
    asm volatile("mma.sync.aligned.m16n8k16.row.col.f32.bf16.bf16.f32 "
        "{%0,%1,%2,%3}, {%4,%5,%6,%7}, {%8,%9}, {%0,%1,%2,%3};"
        : "+f"(c[0]), "+f"(c[1]), "+f"(c[2]), "+f"(c[3])
        : "r"(a[0]), "r"(a[1]), "r"(a[2]), "r"(a[3]), "r"(b[0]), "r"(b[1]));
}
#define CP16(sm, gp) asm volatile("cp.async.cg.shared.global [%0], [%1], 16;" :: "r"(sm), "l"(gp))
#define CP_COMMIT()  asm volatile("cp.async.commit_group;" ::: "memory")
#define CP_WAIT1()   asm volatile("cp.async.wait_group 1;" ::: "memory")
#define CP_WAIT0()   asm volatile("cp.async.wait_group 0;" ::: "memory")

// byte offset of (row, kc) 16B-unit in a [128 x 32bf16] tile, xor-swizzled
__device__ __forceinline__ uint32_t tunit(int row, int kc) {
    return (uint32_t)((row*4 + (kc ^ ((row >> 1) & 3))) * 16);
}

// ======================= static scratch ===================================
__device__ float g_mixed[NTOK*MIXW];        // [qkv | z]
__device__ float g_beta[NTOK*HV_];
__device__ float g_gg[NTOK*HV_];
__device__ float g_qn[NTOK*HK_*64];
__device__ float g_kn[NTOK*HK_*64];
__device__ float g_v[NTOK*VDIM_];
__device__ float g_o[NTOK*VDIM_];
__device__ __nv_bfloat16 g_hid_h[NTOK*D_],  g_hid_l[NTOK*D_];
__device__ __nv_bfloat16 g_w1_h[MIXW*D_],   g_w1_l[MIXW*D_];     // [N=3072, K=1024]
__device__ __nv_bfloat16 g_wo_h[D_*VDIM_],  g_wo_l[D_*VDIM_];
__device__ __nv_bfloat16 g_on_h[NTOK*VDIM_], g_on_l[NTOK*VDIM_];

// ======================= fp32 -> bf16 hi/lo ===============================
__global__ __launch_bounds__(256) void cvt_hilo(const float* __restrict__ src,
        __nv_bfloat16* __restrict__ hi, __nv_bfloat16* __restrict__ lo, int n4)
{
    int i = blockIdx.x*256 + threadIdx.x;
    if (i >= n4) return;
    float4 x = ((const float4*)src)[i];
    __nv_bfloat16 h0 = __float2bfloat16(x.x), h1 = __float2bfloat16(x.y);
    __nv_bfloat16 h2 = __float2bfloat16(x.z), h3 = __float2bfloat16(x.w);
    __nv_bfloat162 hh0 = {h0,h1}, hh1 = {h2,h3};
    __nv_bfloat162 ll0 = {__float2bfloat16(x.x - __bfloat162float(h0)),
                          __float2bfloat16(x.y - __bfloat162float(h1))};
    __nv_bfloat162 ll1 = {__float2bfloat16(x.z - __bfloat162float(h2)),
                          __float2bfloat16(x.w - __bfloat162float(h3))};
    ((__nv_bfloat162*)hi)[2*i]   = hh0; ((__nv_bfloat162*)hi)[2*i+1] = hh1;
    ((__nv_bfloat162*)lo)[2*i]   = ll0; ((__nv_bfloat162*)lo)[2*i+1] = ll1;
}

// ============ transpose + convert: W[K,N] fp32 -> Wt[N,K] bf16 hi/lo ======
__global__ __launch_bounds__(256) void tconv_hilo(const float* __restrict__ W,
        __nv_bfloat16* __restrict__ thi, __nv_bfloat16* __restrict__ tlo, int K, int N)
{
    __shared__ float tile[32][33];
    int n0 = blockIdx.x*32, k0 = blockIdx.y*32;
    int tx = threadIdx.x, ty = threadIdx.y;   // 32 x 8
    #pragma unroll
    for (int j = 0; j < 32; j += 8)
        tile[ty+j][tx] = W[(long)(k0+ty+j)*N + n0 + tx];
    __syncthreads();
    #pragma unroll
    for (int j = 0; j < 32; j += 8) {
        float x = tile[tx][ty+j];
        __nv_bfloat16 h = __float2bfloat16(x);
        long o = (long)(n0+ty+j)*K + k0 + tx;
        thi[o] = h;
        tlo[o] = __float2bfloat16(x - __bfloat162float(h));
    }
}

// =============== bf16 hi/lo (3-MMA) tensor-core GEMM ======================
#define STAGE_B 32768   // Ah 8K | Al 8K | Bh 8K | Bl 8K
__global__ __launch_bounds__(256) void gemm_mma(
    const __nv_bfloat16* __restrict__ Ah, const __nv_bfloat16* __restrict__ Al,
    const __nv_bfloat16* __restrict__ Bh, const __nv_bfloat16* __restrict__ Bl,
    float* __restrict__ C, int M, int N, int K)
{
    extern __shared__ __align__(128) char smem[];
    uint32_t sb = smem_to_u32(smem);
    int tid = threadIdx.x, lane = tid & 31, wid = tid >> 5;
    int wm = wid & 3, wn = wid >> 2;        // 4 x 2 warp grid
    int bx = blockIdx.x, by = blockIdx.y;
    const int NC = K >> 5;

    float acc[2][8][4];
    #pragma unroll
    for (int i = 0; i < 2; i++)
        #pragma unroll
        for (int j = 0; j < 8; j++)
            #pragma unroll
            for (int q = 0; q < 4; q++) acc[i][j][q] = 0.f;

    int ur[2], uk[2];
    ur[0] = tid >> 2;         uk[0] = tid & 3;
    ur[1] = (tid + 256) >> 2; uk[1] = tid & 3;

    #define LOAD_CHUNK(ic, s) do { \
        long kof = (long)(ic) * 32; \
        uint32_t st = sb + (s)*STAGE_B; \
        _Pragma("unroll") \
        for (int uu = 0; uu < 2; uu++) { \
            int row = ur[uu], kc = uk[uu]; \
            uint32_t d = st + tunit(row, kc); \
            long ao = (long)(by*128 + row)*K + kof + kc*8; \
            long bo = (long)(bx*128 + row)*K + kof + kc*8; \
            CP16(d,         Ah + ao); \
            CP16(d + 8192,  Al + ao); \
            CP16(d + 16384, Bh + bo); \
            CP16(d + 24576, Bl + bo); \
        } \
        CP_COMMIT(); \
    } while (0)

    LOAD_CHUNK(0, 0);

    int lr = lane & 15, lk = lane >> 4;
    for (int ic = 0; ic < NC; ic++) {
        int s = ic & 1;
        if (ic + 1 < NC) { LOAD_CHUNK(ic + 1, s ^ 1); CP_WAIT1(); }
        else             { CP_WAIT0(); }
        __syncthreads();

        uint32_t pAh = sb + s*STAGE_B, pAl = pAh + 8192;
        uint32_t pBh = pAh + 16384,    pBl = pAh + 24576;
        #pragma unroll
        for (int ks = 0; ks < 2; ks++) {
            uint32_t ah[2][4], al[2][4], bh[8][2], bl[8][2];
            #pragma unroll
            for (int mt = 0; mt < 2; mt++) {
                uint32_t off = tunit(wm*32 + mt*16 + lr, ks*2 + lk);
                ldsm_x4(ah[mt], pAh + off);
                ldsm_x4(al[mt], pAl + off);
            }
            #pragma unroll
            for (int bp = 0; bp < 4; bp++) {
                uint32_t off = tunit(wn*64 + bp*16 + lr, ks*2 + lk);
                uint32_t t[4];
                ldsm_x4(t, pBh + off);
                bh[bp*2][0]=t[0]; bh[bp*2][1]=t[2]; bh[bp*2+1][0]=t[1]; bh[bp*2+1][1]=t[3];
                ldsm_x4(t, pBl + off);
                bl[bp*2][0]=t[0]; bl[bp*2][1]=t[2]; bl[bp*2+1][0]=t[1]; bl[bp*2+1][1]=t[3];
            }
            #pragma unroll
            for (int mt = 0; mt < 2; mt++)
                #pragma unroll
                for (int nt = 0; nt < 8; nt++) {
                    mma16816(acc[mt][nt], ah[mt], bh[nt]);
                    mma16816(acc[mt][nt], ah[mt], bl[nt]);
                    mma16816(acc[mt][nt], al[mt], bh[nt]);
                }
        }
        __syncthreads();
    }

    #pragma unroll
    for (int mt = 0; mt < 2; mt++)
        #pragma unroll
        for (int nt = 0; nt < 8; nt++) {
            long r = by*128 + wm*32 + mt*16 + (lane >> 2);
            long c = bx*128 + wn*64 + nt*8 + (lane & 3)*2;
            *(float2*)&C[r*N + c]       = make_float2(acc[mt][nt][0], acc[mt][nt][1]);
            *(float2*)&C[(r+8)*N + c]   = make_float2(acc[mt][nt][2], acc[mt][nt][3]);
        }
}

// ======================= beta / g projections =============================
__global__ __launch_bounds__(256) void betag_kernel(
    const float* __restrict__ hid, const float* __restrict__ Wb,
    const float* __restrict__ Wa, const float* __restrict__ dtb,
    const float* __restrict__ Alog)
{
    int row = blockIdx.x;
    int tid = threadIdx.x;
    __shared__ float sh[D_];
    __shared__ float red[256];
    *(float4*)&sh[tid*4] = *(const float4*)(hid + (long)row*D_ + tid*4);
    __syncthreads();
    int c  = tid & 31, sg = tid >> 5;
    const float* W = (c < 16) ? Wb : Wa;
    int cc = c & 15, k0 = sg * 128;
    float acc = 0.f;
    #pragma unroll 8
    for (int k = 0; k < 128; k++)
        acc = fmaf(sh[k0 + k], W[(k0 + k)*HV_ + cc], acc);
    red[tid] = acc;
    __syncthreads();
    if (tid < 32) {
        float s = 0.f;
        #pragma unroll
        for (int si = 0; si < 8; si++) s += red[si*32 + c];
        if (c < 16) g_beta[(long)row*HV_ + cc] = 1.f / (1.f + expf(-s));
        else {
            float x  = s + dtb[cc];
            float sp = (x > 20.f) ? x : log1pf(expf(x));
            g_gg[(long)row*HV_ + cc] = -expf(Alog[cc]) * sp;
        }
    }
}

// ============== causal conv + SiLU + split + l2norm =======================
__global__ __launch_bounds__(256) void conv_kernel(const float* __restrict__ convw)
{
    int t = blockIdx.x, b = blockIdx.y;
    int tid = threadIdx.x;
    long row = (long)(b*T_ + t);
    __shared__ float sy[CONVD];
    #pragma unroll
    for (int j = 0; j < 8; j++) {
        int c = tid + j*256;
        float4 w = *(const float4*)(convw + c*4);
        float acc = g_mixed[row*MIXW + c] * w.w;
        if (t >= 1) acc = fmaf(g_mixed[(row-1)*MIXW + c], w.z, acc);
        if (t >= 2) acc = fmaf(g_mixed[(row-2)*MIXW + c], w.y, acc);
        if (t >= 3) acc = fmaf(g_mixed[(row-3)*MIXW + c], w.x, acc);
        sy[c] = acc / (1.f + expf(-acc));
    }
    __syncthreads();
    int wrp = tid >> 5, lane = tid & 31;
    {
        float y0 = sy[wrp*64 + lane], y1 = sy[wrp*64 + 32 + lane];
        float ss = y0*y0 + y1*y1;
        #pragma unroll
        for (int off = 16; off; off >>= 1) ss += __shfl_xor_sync(0xffffffffu, ss, off);
        float rs = rsqrtf(ss + EPS_) * 0.125f;
        g_qn[(row*HK_ + wrp)*64 + lane]      = y0 * rs;
        g_qn[(row*HK_ + wrp)*64 + 32 + lane] = y1 * rs;
    }
    {
        float y0 = sy[KDIM_ + wrp*64 + lane], y1 = sy[KDIM_ + wrp*64 + 32 + lane];
        float ss = y0*y0 + y1*y1;
        #pragma unroll
        for (int off = 16; off; off >>= 1) ss += __shfl_xor_sync(0xffffffffu, ss, off);
        float rs = rsqrtf(ss + EPS_);
        g_kn[(row*HK_ + wrp)*64 + lane]      = y0 * rs;
        g_kn[(row*HK_ + wrp)*64 + 32 + lane] = y1 * rs;
    }
    #pragma unroll
    for (int j = 0; j < 4; j++) {
        int c = tid + j*256;
        g_v[row*VDIM_ + c] = sy[1024 + c];
    }
}

// ======= gated delta recurrence: warp-autonomous, shfl reductions =========
// 512 warps: (b,h) x col-group-of-4. lane = (colIdx 0..3, rseg 0..7).
// S: 8 rows x 1 col per lane. Lazy rank-1 update folded into decay.
__global__ __launch_bounds__(128) void recurrence_kernel()
{
    int w = blockIdx.x*4 + (threadIdx.x >> 5);    // 0..511
    int lane = threadIdx.x & 31;
    int bh = w >> 4, cg = w & 15;
    int b = bh >> 4, h = bh & 15, kh = h >> 1;
    int colIdx = lane >> 3, rseg = lane & 7;
    int col = cg*4 + colIdx;

    const float* kb = g_kn   + ((long)(b*T_)*HK_ + kh)*64 + rseg*8;
    const float* qb = g_qn   + ((long)(b*T_)*HK_ + kh)*64 + rseg*8;
    const float* vb = g_v    + ((long)(b*T_)*HV_ + h)*64 + col;
    const float* gb = g_gg   + (long)(b*T_)*HV_ + h;
    const float* bb = g_beta + (long)(b*T_)*HV_ + h;
    float*       ob = g_o    + ((long)(b*T_)*HV_ + h)*64 + col;
    const long qs = (long)HK_*64, vs = (long)HV_*64, gs = HV_;

    float S[8], kprev[8], dprev = 0.f;
    #pragma unroll
    for (int i = 0; i < 8; i++) { S[i] = 0.f; kprev[i] = 0.f; }

    float4 k0 = *(const float4*)kb,     k1 = *(const float4*)(kb + 4);
    float4 q0 = *(const float4*)qb,     q1 = *(const float4*)(qb + 4);
    float vv = *vb, gv = *gb, bv = *bb;

    for (int t = 0; t < T_; t++) {
        float4 nk0, nk1, nq0, nq1; float nv = 0.f, ng = 0.f, nb2 = 0.f;
        if (t + 1 < T_) {
            long o1 = (long)(t + 1);
            nk0 = *(const float4*)(kb + o1*qs);  nk1 = *(const float4*)(kb + o1*qs + 4);
            nq0 = *(const float4*)(qb + o1*qs);  nq1 = *(const float4*)(qb + o1*qs + 4);
            nv  = vb[o1*vs];  ng = gb[o1*gs];  nb2 = bb[o1*gs];
        } else { nk0 = nk1 = nq0 = nq1 = make_float4(0.f,0.f,0.f,0.f); }

        float eg = expf(gv);
        float kc[8] = {k0.x,k0.y,k0.z,k0.w,k1.x,k1.y,k1.z,k1.w};
        float qc[8] = {q0.x,q0.y,q0.z,q0.w,q1.x,q1.y,q1.z,q1.w};
        float kvp = 0.f, op = 0.f, qkp = 0.f;
        #pragma unroll
        for (int i = 0; i < 8; i++) {
            S[i] = fmaf(kprev[i], dprev, S[i]) * eg;   // deferred update + decay
            kvp  = fmaf(kc[i], S[i], kvp);
            op   = fmaf(qc[i], S[i], op);
            qkp  = fmaf(qc[i], kc[i], qkp);
            kprev[i] = kc[i];
        }
        #pragma unroll
        for (int off = 1; off < 8; off <<= 1) {
            kvp += __shfl_xor_sync(0xffffffffu, kvp, off);
            op  += __shfl_xor_sync(0xffffffffu, op,  off);
            qkp += __shfl_xor_sync(0xffffffffu, qkp, off);
        }
        float delta = (vv - kvp) * bv;
        if (rseg == 0) ob[(long)t*vs] = fmaf(qkp, delta, op);
        dprev = delta;
        k0 = nk0; k1 = nk1; q0 = nq0; q1 = nq1; vv = nv; gv = ng; bv = nb2;
    }
}

// ========== gated RMSNorm * silu(z), emits bf16 hi/lo for GEMM3 ===========
__global__ __launch_bounds__(256) void gnorm_kernel(const float* __restrict__ nw)
{
    int t = blockIdx.x, b = blockIdx.y;
    long row = (long)(b*T_ + t);
    int wrp = threadIdx.x >> 5, lane = threadIdx.x & 31;
    #pragma unroll
    for (int hh = wrp; hh < HV_; hh += 8) {
        float o0 = g_o[(row*HV_ + hh)*64 + lane];
        float o1 = g_o[(row*HV_ + hh)*64 + 32 + lane];
        float ss = o0*o0 + o1*o1;
        #pragma unroll
        for (int off = 16; off; off >>= 1) ss += __shfl_xor_sync(0xffffffffu, ss, off);
        float rs = rsqrtf(ss * (1.f/64.f) + EPS_);
        float z0 = g_mixed[row*MIXW + CONVD + hh*64 + lane];
        float z1 = g_mixed[row*MIXW + CONVD + hh*64 + 32 + lane];
        float v0 = o0 * rs * nw[lane]      * (z0 / (1.f + expf(-z0)));
        float v1 = o1 * rs * nw[lane + 32] * (z1 / (1.f + expf(-z1)));
        long i0 = row*VDIM_ + hh*64 + lane;
        __nv_bfloat16 h0 = __float2bfloat16(v0);
        __nv_bfloat16 h1 = __float2bfloat16(v1);
        g_on_h[i0]      = h0;
        g_on_h[i0 + 32] = h1;
        g_on_l[i0]      = __float2bfloat16(v0 - __bfloat162float(h0));
        g_on_l[i0 + 32] = __float2bfloat16(v1 - __bfloat162float(h1));
    }
}

// ==========================================================================
extern "C" void kernel_launch(void* const* d_in, const int* in_sizes, int n_in,
                              void* d_out, int out_size)
{
    (void)in_sizes; (void)n_in; (void)out_size;
    const float* hid   = (const float*)d_in[0];
    const float* Wqkv  = (const float*)d_in[1];
    const float* Wz    = (const float*)d_in[2];
    const float* Wb    = (const float*)d_in[3];
    const float* Wa    = (const float*)d_in[4];
    const float* dtb   = (const float*)d_in[5];
    const float* Alog  = (const float*)d_in[6];
    const float* convw = (const float*)d_in[7];
    const float* nw    = (const float*)d_in[8];
    const float* Wout  = (const float*)d_in[9];
    float* out = (float*)d_out;

    float *mixed;
    __nv_bfloat16 *hh, *hl, *w1h, *w1l, *woh, *wol, *onh, *onl;
    cudaGetSymbolAddress((void**)&mixed, g_mixed);
    cudaGetSymbolAddress((void**)&hh,  g_hid_h);  cudaGetSymbolAddress((void**)&hl,  g_hid_l);
    cudaGetSymbolAddress((void**)&w1h, g_w1_h);   cudaGetSymbolAddress((void**)&w1l, g_w1_l);
    cudaGetSymbolAddress((void**)&woh, g_wo_h);   cudaGetSymbolAddress((void**)&wol, g_wo_l);
    cudaGetSymbolAddress((void**)&onh, g_on_h);   cudaGetSymbolAddress((void**)&onl, g_on_l);

    static int smem_set = 0;
    if (!smem_set) {
        cudaFuncSetAttribute(gemm_mma, cudaFuncAttributeMaxDynamicSharedMemorySize, 2*STAGE_B);
        smem_set = 1;
    }

    // conversions (Wqkv -> cols [0,2048), Wz -> cols [2048,3072) of combined W)
    cvt_hilo<<<(NTOK*D_/4 + 255)/256, 256>>>(hid, hh, hl, NTOK*D_/4);
    tconv_hilo<<<dim3(CONVD/32, D_/32), dim3(32,8)>>>(Wqkv, w1h, w1l, D_, CONVD);
    tconv_hilo<<<dim3(VDIM_/32, D_/32), dim3(32,8)>>>(Wz, w1h + (long)CONVD*D_, w1l + (long)CONVD*D_, D_, VDIM_);
    tconv_hilo<<<dim3(D_/32, VDIM_/32), dim3(32,8)>>>(Wout, woh, wol, VDIM_, D_);

    // fused GEMM: [mixed | z] = hid @ [Wqkv | Wz]
    gemm_mma<<<dim3(MIXW/128, NTOK/128), 256, 2*STAGE_B>>>(hh, hl, w1h, w1l, mixed, NTOK, MIXW, D_);
    // beta / g
    betag_kernel<<<NTOK, 256>>>(hid, Wb, Wa, dtb, Alog);
    // conv + silu + split + l2norm
    conv_kernel<<<dim3(T_, B_), 256>>>(convw);
    // recurrence (warp-autonomous)
    recurrence_kernel<<<128, 128>>>();
    // gated RMSNorm -> bf16 hi/lo
    gnorm_kernel<<<dim3(T_, B_), 256>>>(nw);
    // GEMM3: out = on @ Wout
    gemm_mma<<<dim3(D_/128, NTOK/128), 256, 2*STAGE_B>>>(onh, onl, woh, wol, out, NTOK, D_, VDIM_);
}

// round 5
// speedup vs baseline: 1.9655x; 1.2363x over previous
#include <cuda_runtime.h>
#include <cuda_fp16.h>
#include <math.h>
#include <stdint.h>

#define B_    2
#define T_    2048
#define D_    1024
#define HV_   16
#define HK_   8
#define KDIM_ 512
#define VDIM_ 1024
#define CONVD 2048
#define MIXW  3072          // fused GEMM width: [qkv 2048 | z 1024]
#define EPS_  1e-6f
#define NTOK  (B_*T_)       // 4096

// ======================= PTX helpers ======================================
__device__ __forceinline__ uint32_t smem_to_u32(const void* p) {
    uint32_t a;
    asm("{ .reg .u64 t; cvta.to.shared.u64 t, %1; cvt.u32.u64 %0, t; }" : "=r"(a) : "l"(p));
    return a;
}
__device__ __forceinline__ void ldsm_x4(uint32_t* r, uint32_t addr) {
    asm volatile("ldmatrix.sync.aligned.m8n8.x4.shared.b16 {%0,%1,%2,%3}, [%4];"
        : "=r"(r[0]), "=r"(r[1]), "=r"(r[2]), "=r"(r[3]) : "r"(addr));
}
__device__ __forceinline__ void mma16816f(float* c, const uint32_t* a, const uint32_t* b) {
    asm volatile("mma.sync.aligned.m16n8k16.row.col.f32.f16.f16.f32 "
        "{%0,%1,%2,%3}, {%4,%5,%6,%7}, {%8,%9}, {%0,%1,%2,%3};"
        : "+f"(c[0]), "+f"(c[1]), "+f"(c[2]), "+f"(c[3])
        : "r"(a[0]), "r"(a[1]), "r"(a[2]), "r"(a[3]), "r"(b[0]), "r"(b[1]));
}
#define CP16(sm, gp) asm volatile("cp.async.cg.shared.global [%0], [%1], 16;" :: "r"(sm), "l"(gp))
#define CP_COMMIT()  asm volatile("cp.async.commit_group;" ::: "memory")
#define CP_WAIT1()   asm volatile("cp.async.wait_group 1;" ::: "memory")
#define CP_WAIT0()   asm volatile("cp.async.wait_group 0;" ::: "memory")

// byte offset of (row, kc) 16B-unit in a [128 x 32fp16] tile, xor-swizzled
__device__ __forceinline__ uint32_t tunit(int row, int kc) {
    return (uint32_t)((row*4 + (kc ^ ((row >> 1) & 3))) * 16);
}

// ======================= static scratch ===================================
__device__ float g_mixed[NTOK*MIXW];        // [qkv | z]
__device__ float g_beta[NTOK*HV_];
__device__ float g_gg[NTOK*HV_];
__device__ float g_qn[NTOK*HK_*64];
__device__ float g_kn[NTOK*HK_*64];
__device__ float g_v[NTOK*VDIM_];
__device__ float g_o[NTOK*VDIM_];
__device__ __half g_hid[NTOK*D_];
__device__ __half g_w1[MIXW*D_];            // [N=3072, K=1024] transposed
__device__ __half g_wo[D_*VDIM_];           // [N=1024, K=1024] transposed
__device__ __half g_on[NTOK*VDIM_];

// ======================= fp32 -> fp16 (elementwise) =======================
__global__ __launch_bounds__(256) void cvt_f2h(const float* __restrict__ src,
        __half* __restrict__ dst, int n4)
{
    int i = blockIdx.x*256 + threadIdx.x;
    if (i >= n4) return;
    float4 x = ((const float4*)src)[i];
    __half2 h0 = __floats2half2_rn(x.x, x.y);
    __half2 h1 = __floats2half2_rn(x.z, x.w);
    ((__half2*)dst)[2*i]   = h0;
    ((__half2*)dst)[2*i+1] = h1;
}

// ============ transpose + convert: W[K,N] fp32 -> Wt[N,K] fp16 ============
__global__ __launch_bounds__(256) void tconv_f2h(const float* __restrict__ W,
        __half* __restrict__ Wt, int K, int N)
{
    __shared__ float tile[32][33];
    int n0 = blockIdx.x*32, k0 = blockIdx.y*32;
    int tx = threadIdx.x, ty = threadIdx.y;   // 32 x 8
    #pragma unroll
    for (int j = 0; j < 32; j += 8)
        tile[ty+j][tx] = W[(long)(k0+ty+j)*N + n0 + tx];
    __syncthreads();
    #pragma unroll
    for (int j = 0; j < 32; j += 8)
        Wt[(long)(n0+ty+j)*K + k0 + tx] = __float2half(tile[tx][ty+j]);
}

// =============== fp16 single-pass tensor-core GEMM =======================
// C[M,N] = A[M,K] @ W[K,N]; A fp16 [M,K] row-major, W fp16 [N,K] row-major.
// 128x128x32 tiles, 256 thr, 3-stage cp.async, 1 sync/chunk, mma.m16n8k16.
#define STAGE_B 16384   // A 8K | B 8K
__global__ __launch_bounds__(256) void gemm_hmma(
    const __half* __restrict__ A, const __half* __restrict__ Bm,
    float* __restrict__ C, int M, int N, int K)
{
    extern __shared__ __align__(128) char smem[];
    uint32_t sb = smem_to_u32(smem);
    int tid = threadIdx.x, lane = tid & 31, wid = tid >> 5;
    int wm = wid & 3, wn = wid >> 2;        // 4 x 2 warp grid (32x64 per warp)
    int bx = blockIdx.x, by = blockIdx.y;
    const int NC = K >> 5;

    float acc[2][8][4];
    #pragma unroll
    for (int i = 0; i < 2; i++)
        #pragma unroll
        for (int j = 0; j < 8; j++)
            #pragma unroll
            for (int q = 0; q < 4; q++) acc[i][j][q] = 0.f;

    #define LOAD_CHUNK(ic, s) do { \
        long kof = (long)(ic) * 32; \
        uint32_t st = sb + (s)*STAGE_B; \
        _Pragma("unroll") \
        for (int j = 0; j < 2; j++) { \
            int u = tid + j*256; \
            int row = u >> 2, kc = u & 3; \
            CP16(st + tunit(row, kc), A + (long)(by*128 + row)*K + kof + kc*8); \
        } \
        _Pragma("unroll") \
        for (int j = 0; j < 2; j++) { \
            int u = tid + j*256; \
            int row = u >> 2, kc = u & 3; \
            CP16(st + 8192 + tunit(row, kc), Bm + (long)(bx*128 + row)*K + kof + kc*8); \
        } \
        CP_COMMIT(); \
    } while (0)

    LOAD_CHUNK(0, 0);
    LOAD_CHUNK(1, 1);

    int lr = lane & 15, lk = lane >> 4;
    for (int ic = 0; ic < NC; ic++) {
        int s = ic - (ic/3)*3;
        if (ic + 1 < NC) CP_WAIT1(); else CP_WAIT0();
        __syncthreads();
        if (ic + 2 < NC) { int s2 = (ic+2) - ((ic+2)/3)*3; LOAD_CHUNK(ic + 2, s2); }

        uint32_t pA = sb + s*STAGE_B, pB = pA + 8192;
        #pragma unroll
        for (int ks = 0; ks < 2; ks++) {
            uint32_t a[2][4], b[8][2];
            #pragma unroll
            for (int mt = 0; mt < 2; mt++)
                ldsm_x4(a[mt], pA + tunit(wm*32 + mt*16 + lr, ks*2 + lk));
            #pragma unroll
            for (int bp = 0; bp < 4; bp++) {
                uint32_t t[4];
                ldsm_x4(t, pB + tunit(wn*64 + bp*16 + lr, ks*2 + lk));
                b[bp*2][0]=t[0]; b[bp*2][1]=t[2]; b[bp*2+1][0]=t[1]; b[bp*2+1][1]=t[3];
            }
            #pragma unroll
            for (int mt = 0; mt < 2; mt++)
                #pragma unroll
                for (int nt = 0; nt < 8; nt++)
                    mma16816f(acc[mt][nt], a[mt], b[nt]);
        }
    }

    #pragma unroll
    for (int mt = 0; mt < 2; mt++)
        #pragma unroll
        for (int nt = 0; nt < 8; nt++) {
            long r = by*128 + wm*32 + mt*16 + (lane >> 2);
            long c = bx*128 + wn*64 + nt*8 + (lane & 3)*2;
            *(float2*)&C[r*N + c]       = make_float2(acc[mt][nt][0], acc[mt][nt][1]);
            *(float2*)&C[(r+8)*N + c]   = make_float2(acc[mt][nt][2], acc[mt][nt][3]);
        }
}

// ======================= beta / g projections =============================
__global__ __launch_bounds__(256) void betag_kernel(
    const float* __restrict__ hid, const float* __restrict__ Wb,
    const float* __restrict__ Wa, const float* __restrict__ dtb,
    const float* __restrict__ Alog)
{
    int row = blockIdx.x;
    int tid = threadIdx.x;
    __shared__ float sh[D_];
    __shared__ float red[256];
    *(float4*)&sh[tid*4] = *(const float4*)(hid + (long)row*D_ + tid*4);
    __syncthreads();
    int c  = tid & 31, sg = tid >> 5;
    const float* W = (c < 16) ? Wb : Wa;
    int cc = c & 15, k0 = sg * 128;
    float acc = 0.f;
    #pragma unroll 8
    for (int k = 0; k < 128; k++)
        acc = fmaf(sh[k0 + k], W[(k0 + k)*HV_ + cc], acc);
    red[tid] = acc;
    __syncthreads();
    if (tid < 32) {
        float s = 0.f;
        #pragma unroll
        for (int si = 0; si < 8; si++) s += red[si*32 + c];
        if (c < 16) g_beta[(long)row*HV_ + cc] = 1.f / (1.f + expf(-s));
        else {
            float x  = s + dtb[cc];
            float sp = (x > 20.f) ? x : log1pf(expf(x));
            g_gg[(long)row*HV_ + cc] = -expf(Alog[cc]) * sp;
        }
    }
}

// ============== causal conv + SiLU + split + l2norm =======================
__global__ __launch_bounds__(256) void conv_kernel(const float* __restrict__ convw)
{
    int t = blockIdx.x, b = blockIdx.y;
    int tid = threadIdx.x;
    long row = (long)(b*T_ + t);
    __shared__ float sy[CONVD];
    #pragma unroll
    for (int j = 0; j < 8; j++) {
        int c = tid + j*256;
        float4 w = *(const float4*)(convw + c*4);
        float acc = g_mixed[row*MIXW + c] * w.w;
        if (t >= 1) acc = fmaf(g_mixed[(row-1)*MIXW + c], w.z, acc);
        if (t >= 2) acc = fmaf(g_mixed[(row-2)*MIXW + c], w.y, acc);
        if (t >= 3) acc = fmaf(g_mixed[(row-3)*MIXW + c], w.x, acc);
        sy[c] = acc / (1.f + __expf(-acc));
    }
    __syncthreads();
    int wrp = tid >> 5, lane = tid & 31;
    {
        float y0 = sy[wrp*64 + lane], y1 = sy[wrp*64 + 32 + lane];
        float ss = y0*y0 + y1*y1;
        #pragma unroll
        for (int off = 16; off; off >>= 1) ss += __shfl_xor_sync(0xffffffffu, ss, off);
        float rs = rsqrtf(ss + EPS_) * 0.125f;
        g_qn[(row*HK_ + wrp)*64 + lane]      = y0 * rs;
        g_qn[(row*HK_ + wrp)*64 + 32 + lane] = y1 * rs;
    }
    {
        float y0 = sy[KDIM_ + wrp*64 + lane], y1 = sy[KDIM_ + wrp*64 + 32 + lane];
        float ss = y0*y0 + y1*y1;
        #pragma unroll
        for (int off = 16; off; off >>= 1) ss += __shfl_xor_sync(0xffffffffu, ss, off);
        float rs = rsqrtf(ss + EPS_);
        g_kn[(row*HK_ + wrp)*64 + lane]      = y0 * rs;
        g_kn[(row*HK_ + wrp)*64 + 32 + lane] = y1 * rs;
    }
    #pragma unroll
    for (int j = 0; j < 4; j++) {
        int c = tid + j*256;
        g_v[row*VDIM_ + c] = sy[1024 + c];
    }
}

// ======= gated delta recurrence: warp-autonomous, shfl reductions =========
__global__ __launch_bounds__(128) void recurrence_kernel()
{
    int w = blockIdx.x*4 + (threadIdx.x >> 5);    // 0..511
    int lane = threadIdx.x & 31;
    int bh = w >> 4, cg = w & 15;
    int b = bh >> 4, h = bh & 15, kh = h >> 1;
    int colIdx = lane >> 3, rseg = lane & 7;
    int col = cg*4 + colIdx;

    const float* kb = g_kn   + ((long)(b*T_)*HK_ + kh)*64 + rseg*8;
    const float* qb = g_qn   + ((long)(b*T_)*HK_ + kh)*64 + rseg*8;
    const float* vb = g_v    + ((long)(b*T_)*HV_ + h)*64 + col;
    const float* gb = g_gg   + (long)(b*T_)*HV_ + h;
    const float* bb = g_beta + (long)(b*T_)*HV_ + h;
    float*       ob = g_o    + ((long)(b*T_)*HV_ + h)*64 + col;
    const long qs = (long)HK_*64, vs = (long)HV_*64, gs = HV_;

    float S[8], kprev[8], dprev = 0.f;
    #pragma unroll
    for (int i = 0; i < 8; i++) { S[i] = 0.f; kprev[i] = 0.f; }

    float4 k0 = *(const float4*)kb,     k1 = *(const float4*)(kb + 4);
    float4 q0 = *(const float4*)qb,     q1 = *(const float4*)(qb + 4);
    float vv = *vb, gv = *gb, bv = *bb;

    for (int t = 0; t < T_; t++) {
        float4 nk0, nk1, nq0, nq1; float nv = 0.f, ng = 0.f, nb2 = 0.f;
        if (t + 1 < T_) {
            long o1 = (long)(t + 1);
            nk0 = *(const float4*)(kb + o1*qs);  nk1 = *(const float4*)(kb + o1*qs + 4);
            nq0 = *(const float4*)(qb + o1*qs);  nq1 = *(const float4*)(qb + o1*qs + 4);
            nv  = vb[o1*vs];  ng = gb[o1*gs];  nb2 = bb[o1*gs];
        } else { nk0 = nk1 = nq0 = nq1 = make_float4(0.f,0.f,0.f,0.f); }

        float eg = __expf(gv);
        float kc[8] = {k0.x,k0.y,k0.z,k0.w,k1.x,k1.y,k1.z,k1.w};
        float qc[8] = {q0.x,q0.y,q0.z,q0.w,q1.x,q1.y,q1.z,q1.w};
        float kvp = 0.f, op = 0.f, qkp = 0.f;
        #pragma unroll
        for (int i = 0; i < 8; i++) {
            S[i] = fmaf(kprev[i], dprev, S[i]) * eg;   // deferred update + decay
            kvp  = fmaf(kc[i], S[i], kvp);
            op   = fmaf(qc[i], S[i], op);
            qkp  = fmaf(qc[i], kc[i], qkp);
            kprev[i] = kc[i];
        }
        #pragma unroll
        for (int off = 1; off < 8; off <<= 1) {
            kvp += __shfl_xor_sync(0xffffffffu, kvp, off);
            op  += __shfl_xor_sync(0xffffffffu, op,  off);
            qkp += __shfl_xor_sync(0xffffffffu, qkp, off);
        }
        float delta = (vv - kvp) * bv;
        if (rseg == 0) ob[(long)t*vs] = fmaf(qkp, delta, op);
        dprev = delta;
        k0 = nk0; k1 = nk1; q0 = nq0; q1 = nq1; vv = nv; gv = ng; bv = nb2;
    }
}

// ========== gated RMSNorm * silu(z), emits fp16 for GEMM3 =================
__global__ __launch_bounds__(256) void gnorm_kernel(const float* __restrict__ nw)
{
    int t = blockIdx.x, b = blockIdx.y;
    long row = (long)(b*T_ + t);
    int wrp = threadIdx.x >> 5, lane = threadIdx.x & 31;
    #pragma unroll
    for (int hh = wrp; hh < HV_; hh += 8) {
        float o0 = g_o[(row*HV_ + hh)*64 + lane];
        float o1 = g_o[(row*HV_ + hh)*64 + 32 + lane];
        float ss = o0*o0 + o1*o1;
        #pragma unroll
        for (int off = 16; off; off >>= 1) ss += __shfl_xor_sync(0xffffffffu, ss, off);
        float rs = rsqrtf(ss * (1.f/64.f) + EPS_);
        float z0 = g_mixed[row*MIXW + CONVD + hh*64 + lane];
        float z1 = g_mixed[row*MIXW + CONVD + hh*64 + 32 + lane];
        float v0 = o0 * rs * nw[lane]      * (z0 / (1.f + __expf(-z0)));
        float v1 = o1 * rs * nw[lane + 32] * (z1 / (1.f + __expf(-z1)));
        long i0 = row*VDIM_ + hh*64 + lane;
        g_on[i0]      = __float2half(v0);
        g_on[i0 + 32] = __float2half(v1);
    }
}

// ==========================================================================
extern "C" void kernel_launch(void* const* d_in, const int* in_sizes, int n_in,
                              void* d_out, int out_size)
{
    (void)in_sizes; (void)n_in; (void)out_size;
    const float* hid   = (const float*)d_in[0];
    const float* Wqkv  = (const float*)d_in[1];
    const float* Wz    = (const float*)d_in[2];
    const float* Wb    = (const float*)d_in[3];
    const float* Wa    = (const float*)d_in[4];
    const float* dtb   = (const float*)d_in[5];
    const float* Alog  = (const float*)d_in[6];
    const float* convw = (const float*)d_in[7];
    const float* nw    = (const float*)d_in[8];
    const float* Wout  = (const float*)d_in[9];
    float* out = (float*)d_out;

    float *mixed;
    __half *hh, *w1, *wo, *on;
    cudaGetSymbolAddress((void**)&mixed, g_mixed);
    cudaGetSymbolAddress((void**)&hh, g_hid);
    cudaGetSymbolAddress((void**)&w1, g_w1);
    cudaGetSymbolAddress((void**)&wo, g_wo);
    cudaGetSymbolAddress((void**)&on, g_on);

    static int smem_set = 0;
    if (!smem_set) {
        cudaFuncSetAttribute(gemm_hmma, cudaFuncAttributeMaxDynamicSharedMemorySize, 3*STAGE_B);
        smem_set = 1;
    }

    // conversions (Wqkv -> rows [0,2048), Wz -> rows [2048,3072) of combined Wt)
    cvt_f2h<<<(NTOK*D_/4 + 255)/256, 256>>>(hid, hh, NTOK*D_/4);
    tconv_f2h<<<dim3(CONVD/32, D_/32), dim3(32,8)>>>(Wqkv, w1, D_, CONVD);
    tconv_f2h<<<dim3(VDIM_/32, D_/32), dim3(32,8)>>>(Wz, w1 + (long)CONVD*D_, D_, VDIM_);
    tconv_f2h<<<dim3(D_/32, VDIM_/32), dim3(32,8)>>>(Wout, wo, VDIM_, D_);

    // fused GEMM: [mixed | z] = hid @ [Wqkv | Wz]
    gemm_hmma<<<dim3(MIXW/128, NTOK/128), 256, 3*STAGE_B>>>(hh, w1, mixed, NTOK, MIXW, D_);
    // beta / g
    betag_kernel<<<NTOK, 256>>>(hid, Wb, Wa, dtb, Alog);
    // conv + silu + split + l2norm
    conv_kernel<<<dim3(T_, B_), 256>>>(convw);
    // recurrence (warp-autonomous)
    recurrence_kernel<<<128, 128>>>();
    // gated RMSNorm -> fp16
    gnorm_kernel<<<dim3(T_, B_), 256>>>(nw);
    // GEMM3: out = on @ Wout
    gemm_hmma<<<dim3(D_/128, NTOK/128), 256, 3*STAGE_B>>>(on, wo, out, NTOK, D_, VDIM_);
}